// round 12
// baseline (speedup 1.0000x reference)
#include <cuda_runtime.h>
#include <cstdint>

#define NJ   23
#define NP   16
#define NT   256            // vertices per CTA (MMA M)
#define SWST 257            // sW row stride: rows disjoint, conflict-free
#define SDST 260            // sD row stride: conflict-free frag stores/reads

// dynamic smem (floats), sD aliases sB/sW after mainloop:
#define SB_FLOATS (96*48)                   // 4608, fragment-packed B
#define SW_OFF    SB_FLOATS                 // 4608
#define SD_FLOATS (48*SDST)                 // 12480 (> 4608 + 24*257 = 10776)
#define SMEM_BYTES (SD_FLOATS*4)            // 49920

__device__ __align__(16) float d_B[96*48];  // fragment-packed pose matrix (tf32)

__constant__ float c_scale[NJ] = {
    0.78539816339744831f, 0.f, 0.f, 1.57079632679489662f, 1.57079632679489662f,
    0.78539816339744831f, 0.f, 0.78539816339744831f, 0.f, 0.78539816339744831f,
    0.f, 1.57079632679489662f, 1.57079632679489662f, 0.78539816339744831f, 0.f,
    0.78539816339744831f, 0.f, 0.78539816339744831f, 0.f, 0.f, 0.f, 0.f, 0.f };
__constant__ int c_slot[NJ] = {0,-1,-1,1,2,3,-1,4,-1,5,-1,6,7,8,-1,9,-1,10,-1,-1,-1,-1,-1};
__constant__ int c_par[NJ]  = {-1,0,1,1,3,4,5,4,7,4,9,1,11,12,13,12,15,12,17,0,19,0,21};

__device__ __forceinline__ float tf32r(float x) {
    uint32_t r; asm("cvt.rna.tf32.f32 %0, %1;" : "=r"(r) : "f"(x));
    return __uint_as_float(r);
}
__device__ __forceinline__ uint32_t tf32u(float x) {
    uint32_t r; asm("cvt.rna.tf32.f32 %0, %1;" : "=r"(r) : "f"(x));
    return r;
}
__device__ __forceinline__ void mma8(float* d, uint32_t a0, uint32_t a1, uint32_t a2,
                                     uint32_t a3, uint32_t b0, uint32_t b1) {
    asm volatile(
        "mma.sync.aligned.m16n8k8.row.col.f32.tf32.tf32.f32 "
        "{%0,%1,%2,%3}, {%4,%5,%6,%7}, {%8,%9}, {%0,%1,%2,%3};"
        : "+f"(d[0]), "+f"(d[1]), "+f"(d[2]), "+f"(d[3])
        : "r"(a0), "r"(a1), "r"(a2), "r"(a3), "r"(b0), "r"(b1));
}

// Fragment-packed index for logical B[k][n] (k = K-row 0..95, n = col 0..47):
//   s = k>>3, which = (k>>2)&1, t = k&3, f = n>>3, g = n&7
//   idx = ((s*4 + t)*8 + g)*12 + 2*f + which
__device__ __forceinline__ int bpack_idx(int k, int n) {
    int s = k >> 3, which = (k >> 2) & 1, t = k & 3;
    int f = n >> 3, g = n & 7;
    return (((s*4 + t)*8 + g)*12) + 2*f + which;
}

// ---------------------------------------------------------------------------
// Kernel 1: pose chain -> d_B (fragment-packed tf32) + out_joints. 1 block.
// ---------------------------------------------------------------------------
__global__ void pose_kernel(const float* __restrict__ joints,
                            const float* __restrict__ disp,
                            const float* __restrict__ rdis,
                            const float* jp0, const float* jp3, const float* jp4,
                            const float* jp5, const float* jp7, const float* jp9,
                            const float* jp11, const float* jp12, const float* jp13,
                            const float* jp15, const float* jp17,
                            float* __restrict__ out_joints)
{
    __shared__ float sT[NP*NJ*12];
    const int tid = threadIdx.x;

    if (tid < NP*NJ) {
        const float* prm[11] = {jp0,jp3,jp4,jp5,jp7,jp9,jp11,jp12,jp13,jp15,jp17};
        int p = tid / NJ, jt = tid - p*NJ;
        float rx = 0.f, ry = 0.f, rz = 0.f;
        int s = c_slot[jt];
        if (s >= 0) {
            float sc = c_scale[jt];
            rx = sc * tanhf(prm[s][p*3+0]);
            ry = sc * tanhf(prm[s][p*3+1]);
            rz = sc * tanhf(prm[s][p*3+2]);
        }
        float ang = sqrtf(rx*rx + ry*ry + rz*rz + 1e-16f);
        float x = rx/ang, y = ry/ang, z = rz/ang;
        float sn = sinf(ang), cs = cosf(ang), t = 1.0f - cs;
        float* T = sT + tid*12;
        T[0] = 1.f - t*(y*y+z*z); T[1] = -sn*z + t*x*y;     T[2] =  sn*y + t*x*z;
        T[3] =  sn*z + t*x*y;     T[4] = 1.f - t*(x*x+z*z); T[5] = -sn*x + t*y*z;
        T[6] = -sn*y + t*x*z;     T[7] =  sn*x + t*y*z;     T[8] = 1.f - t*(x*x+y*y);
        int par = c_par[jt];
        if (par < 0) { T[9]=joints[0]; T[10]=joints[1]; T[11]=joints[2]; }
        else {
            T[9]  = joints[jt*3+0] - joints[par*3+0];
            T[10] = joints[jt*3+1] - joints[par*3+1];
            T[11] = joints[jt*3+2] - joints[par*3+2];
        }
    }
    __syncthreads();

    if (tid < NP*NJ) {
        int p = tid / NJ, jt = tid - p*NJ;
        float shf[3];
#pragma unroll
        for (int k = 0; k < 3; k++)
            shf[k] = rdis[p*3+k] + 3.0f * tanhf(disp[p*3+k]);

        int chain[8], d = 0, a = jt;
        while (a >= 0) { chain[d++] = a; a = c_par[a]; }

        float G[12];
        {
            const float* Tr = sT + (p*NJ + chain[d-1])*12;
#pragma unroll
            for (int q = 0; q < 12; q++) G[q] = Tr[q];
        }
        for (int q = d - 2; q >= 0; q--) {
            const float* T = sT + (p*NJ + chain[q])*12;
            float N_[12];
#pragma unroll
            for (int i = 0; i < 3; i++) {
#pragma unroll
                for (int k = 0; k < 3; k++)
                    N_[i*3+k] = G[i*3]*T[k] + G[i*3+1]*T[3+k] + G[i*3+2]*T[6+k];
                N_[9+i] = G[i*3]*T[9] + G[i*3+1]*T[10] + G[i*3+2]*T[11] + G[9+i];
            }
#pragma unroll
            for (int q2 = 0; q2 < 12; q2++) G[q2] = N_[q2];
        }

        float jx = joints[jt*3], jy = joints[jt*3+1], jz = joints[jt*3+2];
#pragma unroll
        for (int i = 0; i < 3; i++) {
            float At = G[9+i] - (G[i*3]*jx + G[i*3+1]*jy + G[i*3+2]*jz) + shf[i];
            int n = 3*p + i;
            d_B[bpack_idx(4*jt + 0, n)] = tf32r(G[i*3+0]);
            d_B[bpack_idx(4*jt + 1, n)] = tf32r(G[i*3+1]);
            d_B[bpack_idx(4*jt + 2, n)] = tf32r(G[i*3+2]);
            d_B[bpack_idx(4*jt + 3, n)] = tf32r(At);
            out_joints[(p*NJ + jt)*3 + i] = G[9+i] + shf[i];
        }
    }
    if (tid < 192) {                      // zero-pad K rows 92..95
        int k = 92 + tid / 48, n = tid % 48;
        d_B[bpack_idx(k, n)] = 0.f;
    }
}

// ---------------------------------------------------------------------------
// Kernel 2: MMA skinning. CTA = 256 verts, 8 warps x (2 m-frags, 6 n-frags).
// B fragments read as 3 x LDS.128 per k-step (conflict-free, 48B lane stride).
// ---------------------------------------------------------------------------
__global__ void __launch_bounds__(256)
lbs_mma(const float* __restrict__ verts, const float* __restrict__ weights,
        float* __restrict__ out, int V)
{
    extern __shared__ float sm[];
    float* sB = sm;                    // fragment-packed, 4608 floats
    float* sW = sm + SW_OFF;           // [24 rows x stride 257]
    float* sD = sm;                    // aliases sB/sW after mainloop

    const int tid  = threadIdx.x;
    const int wid  = tid >> 5;
    const int lane = tid & 31;
    const int g    = lane >> 2;
    const int tig  = lane & 3;
    const int v0   = blockIdx.x * NT;

    // stage B: pure linear float4 copy (no index math)
    for (int t = tid; t < SB_FLOATS/4; t += 256)
        ((float4*)sB)[t] = ((const float4*)d_B)[t];
    // stage weights transposed: sW[j][v] (coalesced gmem, rows disjoint)
    {
        int nv = V - v0; if (nv > NT) nv = NT;
        for (int t = tid; t < NT*NJ; t += 256) {
            int v = t / NJ, j = t - v*NJ;
            sW[j*SWST + v] = (v < nv) ? weights[(size_t)(v0 + v)*NJ + j] : 0.f;
        }
    }
    __syncthreads();

    // vertex components for this lane's 4 rows (r0, r0+8, r0+16, r0+24)
    const int r0 = wid*32 + g;
    float comp[4];
#pragma unroll
    for (int q = 0; q < 4; q++) {
        int vg = v0 + r0 + 8*q;
        comp[q] = (tig == 3) ? 1.0f
                : (vg < V ? verts[(size_t)vg*3 + tig] : 0.f);
    }

    float acc[2][6][4];
#pragma unroll
    for (int m = 0; m < 2; m++)
#pragma unroll
        for (int f = 0; f < 6; f++)
#pragma unroll
            for (int q = 0; q < 4; q++) acc[m][f][q] = 0.f;

    const float4* sB4 = (const float4*)sB;
    const int lslot = (tig*8 + g)*3;          // lane's float4 slot within a k-step
#pragma unroll
    for (int s = 0; s < 12; s++) {
        int j0 = 2*s, j1 = 2*s + 1;
        float w0[4], w1[4];
#pragma unroll
        for (int q = 0; q < 4; q++) {
            w0[q] = sW[j0*SWST + r0 + 8*q];
            w1[q] = (j1 < NJ) ? sW[j1*SWST + r0 + 8*q] : 0.f;
        }
        uint32_t a[2][4];
#pragma unroll
        for (int m = 0; m < 2; m++) {
            a[m][0] = tf32u(w0[2*m]   * comp[2*m]);
            a[m][1] = tf32u(w0[2*m+1] * comp[2*m+1]);
            a[m][2] = tf32u(w1[2*m]   * comp[2*m]);
            a[m][3] = tf32u(w1[2*m+1] * comp[2*m+1]);
        }
        // 3 x LDS.128: {b0(f),b1(f)} pairs for f = 0..5
        float4 q0 = sB4[s*96 + lslot + 0];
        float4 q1 = sB4[s*96 + lslot + 1];
        float4 q2 = sB4[s*96 + lslot + 2];
        uint32_t b0[6] = { __float_as_uint(q0.x), __float_as_uint(q0.z),
                           __float_as_uint(q1.x), __float_as_uint(q1.z),
                           __float_as_uint(q2.x), __float_as_uint(q2.z) };
        uint32_t b1[6] = { __float_as_uint(q0.y), __float_as_uint(q0.w),
                           __float_as_uint(q1.y), __float_as_uint(q1.w),
                           __float_as_uint(q2.y), __float_as_uint(q2.w) };
#pragma unroll
        for (int f = 0; f < 6; f++) {
            mma8(acc[0][f], a[0][0], a[0][1], a[0][2], a[0][3], b0[f], b1[f]);
            mma8(acc[1][f], a[1][0], a[1][1], a[1][2], a[1][3], b0[f], b1[f]);
        }
    }

    // stage D into smem (aliases sB/sW; conflict-free: bank = (8*tig+g)&31)
    __syncthreads();
#pragma unroll
    for (int m = 0; m < 2; m++) {
        int rA = r0 + 16*m, rB = rA + 8;
#pragma unroll
        for (int f = 0; f < 6; f++) {
            int n0 = 8*f + 2*tig;
            sD[ n0      *SDST + rA] = acc[m][f][0];
            sD[(n0 + 1) *SDST + rA] = acc[m][f][1];
            sD[ n0      *SDST + rB] = acc[m][f][2];
            sD[(n0 + 1) *SDST + rB] = acc[m][f][3];
        }
    }
    __syncthreads();

    // epilogue: warp wid -> poses 2wid, 2wid+1; lane = vertex; 12B-contig STG
#pragma unroll
    for (int pp = 0; pp < 2; pp++) {
        int p = wid*2 + pp;
#pragma unroll
        for (int c = 0; c < 8; c++) {
            int vl = c*32 + lane;
            int vg = v0 + vl;
            if (vg < V) {
                float o0 = sD[(3*p + 0)*SDST + vl];
                float o1 = sD[(3*p + 1)*SDST + vl];
                float o2 = sD[(3*p + 2)*SDST + vl];
                float* dst = out + ((size_t)p*V + vg)*3;
                dst[0] = o0; dst[1] = o1; dst[2] = o2;
            }
        }
    }
}

// ---------------------------------------------------------------------------
extern "C" void kernel_launch(void* const* d_in, const int* in_sizes, int n_in,
                              void* d_out, int out_size)
{
    const float* verts   = (const float*)d_in[0];
    const float* joints  = (const float*)d_in[1];
    const float* weights = (const float*)d_in[2];
    const float* disp    = (const float*)d_in[3];
    const float* rdis    = (const float*)d_in[4];

    int V = in_sizes[0] / 3;
    float* out = (float*)d_out;
    float* out_joints = out + (size_t)out_size - (size_t)NP * NJ * 3;

    cudaFuncSetAttribute(lbs_mma, cudaFuncAttributeMaxDynamicSharedMemorySize, SMEM_BYTES);

    pose_kernel<<<1, 384>>>(joints, disp, rdis,
                            (const float*)d_in[5],  (const float*)d_in[6],
                            (const float*)d_in[7],  (const float*)d_in[8],
                            (const float*)d_in[9],  (const float*)d_in[10],
                            (const float*)d_in[11], (const float*)d_in[12],
                            (const float*)d_in[13], (const float*)d_in[14],
                            (const float*)d_in[15],
                            out_joints);

    int blocks = (V + NT - 1) / NT;
    lbs_mma<<<blocks, 256, SMEM_BYTES>>>(verts, weights, out, V);
}

// round 13
// speedup vs baseline: 1.0592x; 1.0592x over previous
#include <cuda_runtime.h>
#include <cstdint>

#define NJ   23
#define NP   16
#define NT   256            // vertices per CTA (MMA M)
#define SWST 26             // sW row stride [v][j]: conflict-free LDS.64 (g*26 mod 32 distinct)
#define SDST 260            // sD row stride: conflict-free frag stores/reads

// dynamic smem (floats), sD aliases sB/sW after mainloop:
#define SB_FLOATS (96*48)                   // 4608, fragment-packed B
#define SW_OFF    SB_FLOATS                 // 4608
#define SD_FLOATS (48*SDST)                 // 12480 (> 4608 + 256*26 = 11264)
#define SMEM_BYTES (SD_FLOATS*4)            // 49920

__device__ __align__(16) float d_B[96*48];  // fragment-packed pose matrix (tf32)

__constant__ float c_scale[NJ] = {
    0.78539816339744831f, 0.f, 0.f, 1.57079632679489662f, 1.57079632679489662f,
    0.78539816339744831f, 0.f, 0.78539816339744831f, 0.f, 0.78539816339744831f,
    0.f, 1.57079632679489662f, 1.57079632679489662f, 0.78539816339744831f, 0.f,
    0.78539816339744831f, 0.f, 0.78539816339744831f, 0.f, 0.f, 0.f, 0.f, 0.f };
__constant__ int c_slot[NJ] = {0,-1,-1,1,2,3,-1,4,-1,5,-1,6,7,8,-1,9,-1,10,-1,-1,-1,-1,-1};
__constant__ int c_par[NJ]  = {-1,0,1,1,3,4,5,4,7,4,9,1,11,12,13,12,15,12,17,0,19,0,21};

__device__ __forceinline__ float tf32r(float x) {
    uint32_t r; asm("cvt.rna.tf32.f32 %0, %1;" : "=r"(r) : "f"(x));
    return __uint_as_float(r);
}
__device__ __forceinline__ uint32_t tf32u(float x) {
    uint32_t r; asm("cvt.rna.tf32.f32 %0, %1;" : "=r"(r) : "f"(x));
    return r;
}
__device__ __forceinline__ void mma8(float* d, uint32_t a0, uint32_t a1, uint32_t a2,
                                     uint32_t a3, uint32_t b0, uint32_t b1) {
    asm volatile(
        "mma.sync.aligned.m16n8k8.row.col.f32.tf32.tf32.f32 "
        "{%0,%1,%2,%3}, {%4,%5,%6,%7}, {%8,%9}, {%0,%1,%2,%3};"
        : "+f"(d[0]), "+f"(d[1]), "+f"(d[2]), "+f"(d[3])
        : "r"(a0), "r"(a1), "r"(a2), "r"(a3), "r"(b0), "r"(b1));
}

// Fragment-packed index for logical B[k][n], k = 0..95, n = 0..47:
//   s = k>>3, which = (k>>2)&1, t = k&3, f = n>>3, g = n&7
//   lane slot = g*4 + t  (== lane id, so LDS.128 lane stride = 12 floats: conflict-free)
//   idx = s*384 + (g*4 + t)*12 + 2*f + which
__device__ __forceinline__ int bpack_idx(int k, int n) {
    int s = k >> 3, which = (k >> 2) & 1, t = k & 3;
    int f = n >> 3, g = n & 7;
    return s*384 + (g*4 + t)*12 + 2*f + which;
}

// ---------------------------------------------------------------------------
// Kernel 1: pose chain -> d_B (fragment-packed tf32) + out_joints. 1 block.
// ---------------------------------------------------------------------------
__global__ void pose_kernel(const float* __restrict__ joints,
                            const float* __restrict__ disp,
                            const float* __restrict__ rdis,
                            const float* jp0, const float* jp3, const float* jp4,
                            const float* jp5, const float* jp7, const float* jp9,
                            const float* jp11, const float* jp12, const float* jp13,
                            const float* jp15, const float* jp17,
                            float* __restrict__ out_joints)
{
    __shared__ float sT[NP*NJ*12];
    const int tid = threadIdx.x;

    if (tid < NP*NJ) {
        const float* prm[11] = {jp0,jp3,jp4,jp5,jp7,jp9,jp11,jp12,jp13,jp15,jp17};
        int p = tid / NJ, jt = tid - p*NJ;
        float rx = 0.f, ry = 0.f, rz = 0.f;
        int s = c_slot[jt];
        if (s >= 0) {
            float sc = c_scale[jt];
            rx = sc * tanhf(prm[s][p*3+0]);
            ry = sc * tanhf(prm[s][p*3+1]);
            rz = sc * tanhf(prm[s][p*3+2]);
        }
        float ang = sqrtf(rx*rx + ry*ry + rz*rz + 1e-16f);
        float x = rx/ang, y = ry/ang, z = rz/ang;
        float sn = sinf(ang), cs = cosf(ang), t = 1.0f - cs;
        float* T = sT + tid*12;
        T[0] = 1.f - t*(y*y+z*z); T[1] = -sn*z + t*x*y;     T[2] =  sn*y + t*x*z;
        T[3] =  sn*z + t*x*y;     T[4] = 1.f - t*(x*x+z*z); T[5] = -sn*x + t*y*z;
        T[6] = -sn*y + t*x*z;     T[7] =  sn*x + t*y*z;     T[8] = 1.f - t*(x*x+y*y);
        int par = c_par[jt];
        if (par < 0) { T[9]=joints[0]; T[10]=joints[1]; T[11]=joints[2]; }
        else {
            T[9]  = joints[jt*3+0] - joints[par*3+0];
            T[10] = joints[jt*3+1] - joints[par*3+1];
            T[11] = joints[jt*3+2] - joints[par*3+2];
        }
    }
    __syncthreads();

    if (tid < NP*NJ) {
        int p = tid / NJ, jt = tid - p*NJ;
        float shf[3];
#pragma unroll
        for (int k = 0; k < 3; k++)
            shf[k] = rdis[p*3+k] + 3.0f * tanhf(disp[p*3+k]);

        int chain[8], d = 0, a = jt;
        while (a >= 0) { chain[d++] = a; a = c_par[a]; }

        float G[12];
        {
            const float* Tr = sT + (p*NJ + chain[d-1])*12;
#pragma unroll
            for (int q = 0; q < 12; q++) G[q] = Tr[q];
        }
        for (int q = d - 2; q >= 0; q--) {
            const float* T = sT + (p*NJ + chain[q])*12;
            float N_[12];
#pragma unroll
            for (int i = 0; i < 3; i++) {
#pragma unroll
                for (int k = 0; k < 3; k++)
                    N_[i*3+k] = G[i*3]*T[k] + G[i*3+1]*T[3+k] + G[i*3+2]*T[6+k];
                N_[9+i] = G[i*3]*T[9] + G[i*3+1]*T[10] + G[i*3+2]*T[11] + G[9+i];
            }
#pragma unroll
            for (int q2 = 0; q2 < 12; q2++) G[q2] = N_[q2];
        }

        float jx = joints[jt*3], jy = joints[jt*3+1], jz = joints[jt*3+2];
#pragma unroll
        for (int i = 0; i < 3; i++) {
            float At = G[9+i] - (G[i*3]*jx + G[i*3+1]*jy + G[i*3+2]*jz) + shf[i];
            int n = 3*p + i;
            d_B[bpack_idx(4*jt + 0, n)] = tf32r(G[i*3+0]);
            d_B[bpack_idx(4*jt + 1, n)] = tf32r(G[i*3+1]);
            d_B[bpack_idx(4*jt + 2, n)] = tf32r(G[i*3+2]);
            d_B[bpack_idx(4*jt + 3, n)] = tf32r(At);
            out_joints[(p*NJ + jt)*3 + i] = G[9+i] + shf[i];
        }
    }
    if (tid < 192) {                      // zero-pad K rows 92..95
        int k = 92 + tid / 48, n = tid % 48;
        d_B[bpack_idx(k, n)] = 0.f;
    }
}

// ---------------------------------------------------------------------------
// Kernel 2: MMA skinning. CTA = 256 verts, 8 warps x (2 m-frags, 6 n-frags).
// B frags: 3 x LDS.128 per k-step (lane stride 12 floats -> conflict-free).
// W: 4 x LDS.64 per k-step (row stride 26 -> conflict-free broadcast).
// ---------------------------------------------------------------------------
__global__ void __launch_bounds__(256)
lbs_mma(const float* __restrict__ verts, const float* __restrict__ weights,
        float* __restrict__ out, int V)
{
    extern __shared__ float sm[];
    float* sB = sm;                    // fragment-packed, 4608 floats
    float* sW = sm + SW_OFF;           // [256 rows x stride 26], col 23 zeroed
    float* sD = sm;                    // aliases sB/sW after mainloop

    const int tid  = threadIdx.x;
    const int wid  = tid >> 5;
    const int lane = tid & 31;
    const int g    = lane >> 2;
    const int tig  = lane & 3;
    const int v0   = blockIdx.x * NT;

    // stage B: pure linear float4 copy (no index math)
    for (int t = tid; t < SB_FLOATS/4; t += 256)
        ((float4*)sB)[t] = ((const float4*)d_B)[t];
    // stage weights: sW[v][j], row stride 26 (same index math as R9, new target)
    {
        int nv = V - v0; if (nv > NT) nv = NT;
        for (int t = tid; t < NT*NJ; t += 256) {
            int v = t / NJ, j = t - v*NJ;
            sW[v*SWST + j] = (v < nv) ? weights[(size_t)(v0 + v)*NJ + j] : 0.f;
        }
        if (tid < NT) sW[tid*SWST + 23] = 0.f;   // pad col j=23
    }
    __syncthreads();

    // vertex components for this lane's 4 rows (r0, r0+8, r0+16, r0+24)
    const int r0 = wid*32 + g;
    float comp[4];
#pragma unroll
    for (int q = 0; q < 4; q++) {
        int vg = v0 + r0 + 8*q;
        comp[q] = (tig == 3) ? 1.0f
                : (vg < V ? verts[(size_t)vg*3 + tig] : 0.f);
    }

    float acc[2][6][4];
#pragma unroll
    for (int m = 0; m < 2; m++)
#pragma unroll
        for (int f = 0; f < 6; f++)
#pragma unroll
            for (int q = 0; q < 4; q++) acc[m][f][q] = 0.f;

    const float4* sB4 = (const float4*)sB;
    const int lslot = lane*3;                 // float4 slot within a k-step
#pragma unroll
    for (int s = 0; s < 12; s++) {
        // 4 x LDS.64: weights (j=2s, 2s+1) for rows r0+8q; j=23 pad gives 0
        float w0[4], w1[4];
#pragma unroll
        for (int q = 0; q < 4; q++) {
            float2 wp = *(const float2*)(sW + (r0 + 8*q)*SWST + 2*s);
            w0[q] = wp.x; w1[q] = wp.y;
        }
        uint32_t a[2][4];
#pragma unroll
        for (int m = 0; m < 2; m++) {
            a[m][0] = tf32u(w0[2*m]   * comp[2*m]);
            a[m][1] = tf32u(w0[2*m+1] * comp[2*m+1]);
            a[m][2] = tf32u(w1[2*m]   * comp[2*m]);
            a[m][3] = tf32u(w1[2*m+1] * comp[2*m+1]);
        }
        // 3 x LDS.128: {b0(f),b1(f)} pairs for f = 0..5 (conflict-free)
        float4 q0 = sB4[s*96 + lslot + 0];
        float4 q1 = sB4[s*96 + lslot + 1];
        float4 q2 = sB4[s*96 + lslot + 2];
        uint32_t b0[6] = { __float_as_uint(q0.x), __float_as_uint(q0.z),
                           __float_as_uint(q1.x), __float_as_uint(q1.z),
                           __float_as_uint(q2.x), __float_as_uint(q2.z) };
        uint32_t b1[6] = { __float_as_uint(q0.y), __float_as_uint(q0.w),
                           __float_as_uint(q1.y), __float_as_uint(q1.w),
                           __float_as_uint(q2.y), __float_as_uint(q2.w) };
#pragma unroll
        for (int f = 0; f < 6; f++) {
            mma8(acc[0][f], a[0][0], a[0][1], a[0][2], a[0][3], b0[f], b1[f]);
            mma8(acc[1][f], a[1][0], a[1][1], a[1][2], a[1][3], b0[f], b1[f]);
        }
    }

    // stage D into smem (aliases sB/sW; conflict-free: bank = (8*tig+g)&31)
    __syncthreads();
#pragma unroll
    for (int m = 0; m < 2; m++) {
        int rA = r0 + 16*m, rB = rA + 8;
#pragma unroll
        for (int f = 0; f < 6; f++) {
            int n0 = 8*f + 2*tig;
            sD[ n0      *SDST + rA] = acc[m][f][0];
            sD[(n0 + 1) *SDST + rA] = acc[m][f][1];
            sD[ n0      *SDST + rB] = acc[m][f][2];
            sD[(n0 + 1) *SDST + rB] = acc[m][f][3];
        }
    }
    __syncthreads();

    // epilogue: warp wid -> poses 2wid, 2wid+1; lane = vertex; 12B-contig STG
#pragma unroll
    for (int pp = 0; pp < 2; pp++) {
        int p = wid*2 + pp;
#pragma unroll
        for (int c = 0; c < 8; c++) {
            int vl = c*32 + lane;
            int vg = v0 + vl;
            if (vg < V) {
                float o0 = sD[(3*p + 0)*SDST + vl];
                float o1 = sD[(3*p + 1)*SDST + vl];
                float o2 = sD[(3*p + 2)*SDST + vl];
                float* dst = out + ((size_t)p*V + vg)*3;
                dst[0] = o0; dst[1] = o1; dst[2] = o2;
            }
        }
    }
}

// ---------------------------------------------------------------------------
extern "C" void kernel_launch(void* const* d_in, const int* in_sizes, int n_in,
                              void* d_out, int out_size)
{
    const float* verts   = (const float*)d_in[0];
    const float* joints  = (const float*)d_in[1];
    const float* weights = (const float*)d_in[2];
    const float* disp    = (const float*)d_in[3];
    const float* rdis    = (const float*)d_in[4];

    int V = in_sizes[0] / 3;
    float* out = (float*)d_out;
    float* out_joints = out + (size_t)out_size - (size_t)NP * NJ * 3;

    cudaFuncSetAttribute(lbs_mma, cudaFuncAttributeMaxDynamicSharedMemorySize, SMEM_BYTES);

    pose_kernel<<<1, 384>>>(joints, disp, rdis,
                            (const float*)d_in[5],  (const float*)d_in[6],
                            (const float*)d_in[7],  (const float*)d_in[8],
                            (const float*)d_in[9],  (const float*)d_in[10],
                            (const float*)d_in[11], (const float*)d_in[12],
                            (const float*)d_in[13], (const float*)d_in[14],
                            (const float*)d_in[15],
                            out_joints);

    int blocks = (V + NT - 1) / NT;
    lbs_mma<<<blocks, 256, SMEM_BYTES>>>(verts, weights, out, V);
}

// round 14
// speedup vs baseline: 1.2996x; 1.2270x over previous
#include <cuda_runtime.h>
#include <cstdint>

#define NJ   23
#define NP   16
#define NT   256            // vertices per CTA (MMA M)
#define SWST 26             // sW row stride [v][j]: conflict-free LDS.64 (g*26 mod 32 distinct)
#define SDST 260            // sD row stride: conflict-free frag stores/reads

// dynamic smem (floats), sD aliases sB/sW after mainloop:
#define SB_FLOATS (96*48)                   // 4608, fragment-packed B
#define SW_OFF    SB_FLOATS                 // 4608
#define SD_FLOATS (48*SDST)                 // 12480 (> 4608 + 256*26 = 11264)
#define SMEM_BYTES (SD_FLOATS*4)            // 49920

__device__ __align__(16) float d_B[96*48];  // fragment-packed pose matrix (tf32)

__constant__ float c_scale[NJ] = {
    0.78539816339744831f, 0.f, 0.f, 1.57079632679489662f, 1.57079632679489662f,
    0.78539816339744831f, 0.f, 0.78539816339744831f, 0.f, 0.78539816339744831f,
    0.f, 1.57079632679489662f, 1.57079632679489662f, 0.78539816339744831f, 0.f,
    0.78539816339744831f, 0.f, 0.78539816339744831f, 0.f, 0.f, 0.f, 0.f, 0.f };
__constant__ int c_slot[NJ] = {0,-1,-1,1,2,3,-1,4,-1,5,-1,6,7,8,-1,9,-1,10,-1,-1,-1,-1,-1};
__constant__ int c_par[NJ]  = {-1,0,1,1,3,4,5,4,7,4,9,1,11,12,13,12,15,12,17,0,19,0,21};

__device__ __forceinline__ float tf32r(float x) {
    uint32_t r; asm("cvt.rna.tf32.f32 %0, %1;" : "=r"(r) : "f"(x));
    return __uint_as_float(r);
}
__device__ __forceinline__ uint32_t tf32u(float x) {
    uint32_t r; asm("cvt.rna.tf32.f32 %0, %1;" : "=r"(r) : "f"(x));
    return r;
}
__device__ __forceinline__ void mma8(float* d, uint32_t a0, uint32_t a1, uint32_t a2,
                                     uint32_t a3, uint32_t b0, uint32_t b1) {
    asm volatile(
        "mma.sync.aligned.m16n8k8.row.col.f32.tf32.tf32.f32 "
        "{%0,%1,%2,%3}, {%4,%5,%6,%7}, {%8,%9}, {%0,%1,%2,%3};"
        : "+f"(d[0]), "+f"(d[1]), "+f"(d[2]), "+f"(d[3])
        : "r"(a0), "r"(a1), "r"(a2), "r"(a3), "r"(b0), "r"(b1));
}

// Fragment-packed index for logical B[k][n], k = 0..95, n = 0..47:
//   s = k>>3, which = (k>>2)&1, t = k&3, f = n>>3, g = n&7
//   lane slot = g*4 + t  (== lane id, so LDS.128 lane stride = 12 floats: conflict-free)
//   idx = s*384 + (g*4 + t)*12 + 2*f + which
__device__ __forceinline__ int bpack_idx(int k, int n) {
    int s = k >> 3, which = (k >> 2) & 1, t = k & 3;
    int f = n >> 3, g = n & 7;
    return s*384 + (g*4 + t)*12 + 2*f + which;
}

// ---------------------------------------------------------------------------
// Kernel 1: pose chain -> d_B (fragment-packed tf32) + out_joints. 1 block.
// ---------------------------------------------------------------------------
__global__ void pose_kernel(const float* __restrict__ joints,
                            const float* __restrict__ disp,
                            const float* __restrict__ rdis,
                            const float* jp0, const float* jp3, const float* jp4,
                            const float* jp5, const float* jp7, const float* jp9,
                            const float* jp11, const float* jp12, const float* jp13,
                            const float* jp15, const float* jp17,
                            float* __restrict__ out_joints)
{
    __shared__ float sT[NP*NJ*12];
    const int tid = threadIdx.x;

    if (tid < NP*NJ) {
        const float* prm[11] = {jp0,jp3,jp4,jp5,jp7,jp9,jp11,jp12,jp13,jp15,jp17};
        int p = tid / NJ, jt = tid - p*NJ;
        float rx = 0.f, ry = 0.f, rz = 0.f;
        int s = c_slot[jt];
        if (s >= 0) {
            float sc = c_scale[jt];
            rx = sc * tanhf(prm[s][p*3+0]);
            ry = sc * tanhf(prm[s][p*3+1]);
            rz = sc * tanhf(prm[s][p*3+2]);
        }
        float ang = sqrtf(rx*rx + ry*ry + rz*rz + 1e-16f);
        float x = rx/ang, y = ry/ang, z = rz/ang;
        float sn = sinf(ang), cs = cosf(ang), t = 1.0f - cs;
        float* T = sT + tid*12;
        T[0] = 1.f - t*(y*y+z*z); T[1] = -sn*z + t*x*y;     T[2] =  sn*y + t*x*z;
        T[3] =  sn*z + t*x*y;     T[4] = 1.f - t*(x*x+z*z); T[5] = -sn*x + t*y*z;
        T[6] = -sn*y + t*x*z;     T[7] =  sn*x + t*y*z;     T[8] = 1.f - t*(x*x+y*y);
        int par = c_par[jt];
        if (par < 0) { T[9]=joints[0]; T[10]=joints[1]; T[11]=joints[2]; }
        else {
            T[9]  = joints[jt*3+0] - joints[par*3+0];
            T[10] = joints[jt*3+1] - joints[par*3+1];
            T[11] = joints[jt*3+2] - joints[par*3+2];
        }
    }
    __syncthreads();

    if (tid < NP*NJ) {
        int p = tid / NJ, jt = tid - p*NJ;
        float shf[3];
#pragma unroll
        for (int k = 0; k < 3; k++)
            shf[k] = rdis[p*3+k] + 3.0f * tanhf(disp[p*3+k]);

        int chain[8], d = 0, a = jt;
        while (a >= 0) { chain[d++] = a; a = c_par[a]; }

        float G[12];
        {
            const float* Tr = sT + (p*NJ + chain[d-1])*12;
#pragma unroll
            for (int q = 0; q < 12; q++) G[q] = Tr[q];
        }
        for (int q = d - 2; q >= 0; q--) {
            const float* T = sT + (p*NJ + chain[q])*12;
            float N_[12];
#pragma unroll
            for (int i = 0; i < 3; i++) {
#pragma unroll
                for (int k = 0; k < 3; k++)
                    N_[i*3+k] = G[i*3]*T[k] + G[i*3+1]*T[3+k] + G[i*3+2]*T[6+k];
                N_[9+i] = G[i*3]*T[9] + G[i*3+1]*T[10] + G[i*3+2]*T[11] + G[9+i];
            }
#pragma unroll
            for (int q2 = 0; q2 < 12; q2++) G[q2] = N_[q2];
        }

        float jx = joints[jt*3], jy = joints[jt*3+1], jz = joints[jt*3+2];
#pragma unroll
        for (int i = 0; i < 3; i++) {
            float At = G[9+i] - (G[i*3]*jx + G[i*3+1]*jy + G[i*3+2]*jz) + shf[i];
            int n = 3*p + i;
            d_B[bpack_idx(4*jt + 0, n)] = tf32r(G[i*3+0]);
            d_B[bpack_idx(4*jt + 1, n)] = tf32r(G[i*3+1]);
            d_B[bpack_idx(4*jt + 2, n)] = tf32r(G[i*3+2]);
            d_B[bpack_idx(4*jt + 3, n)] = tf32r(At);
            out_joints[(p*NJ + jt)*3 + i] = G[9+i] + shf[i];
        }
    }
    if (tid < 192) {                      // zero-pad K rows 92..95
        int k = 92 + tid / 48, n = tid % 48;
        d_B[bpack_idx(k, n)] = 0.f;
    }
}

// ---------------------------------------------------------------------------
// Kernel 2: MMA skinning. CTA = 256 verts, 8 warps x (2 m-frags, 6 n-frags).
// B frags: 3 x LDS.128 per k-step (lane stride 12 floats -> conflict-free).
// W: 4 x LDS.64 per k-step (row stride 26 -> conflict-free broadcast).
// __launch_bounds__(256, 3): cap regs at 84 so 3 CTAs/SM stay resident.
// ---------------------------------------------------------------------------
__global__ void __launch_bounds__(256, 3)
lbs_mma(const float* __restrict__ verts, const float* __restrict__ weights,
        float* __restrict__ out, int V)
{
    extern __shared__ float sm[];
    float* sB = sm;                    // fragment-packed, 4608 floats
    float* sW = sm + SW_OFF;           // [256 rows x stride 26], col 23 zeroed
    float* sD = sm;                    // aliases sB/sW after mainloop

    const int tid  = threadIdx.x;
    const int wid  = tid >> 5;
    const int lane = tid & 31;
    const int g    = lane >> 2;
    const int tig  = lane & 3;
    const int v0   = blockIdx.x * NT;

    // stage B: pure linear float4 copy (no index math)
    for (int t = tid; t < SB_FLOATS/4; t += 256)
        ((float4*)sB)[t] = ((const float4*)d_B)[t];
    // stage weights: sW[v][j], row stride 26
    {
        int nv = V - v0; if (nv > NT) nv = NT;
        for (int t = tid; t < NT*NJ; t += 256) {
            int v = t / NJ, j = t - v*NJ;
            sW[v*SWST + j] = (v < nv) ? weights[(size_t)(v0 + v)*NJ + j] : 0.f;
        }
        if (tid < NT) sW[tid*SWST + 23] = 0.f;   // pad col j=23
    }
    __syncthreads();

    // vertex components for this lane's 4 rows (r0, r0+8, r0+16, r0+24)
    const int r0 = wid*32 + g;
    float comp[4];
#pragma unroll
    for (int q = 0; q < 4; q++) {
        int vg = v0 + r0 + 8*q;
        comp[q] = (tig == 3) ? 1.0f
                : (vg < V ? verts[(size_t)vg*3 + tig] : 0.f);
    }

    float acc[2][6][4];
#pragma unroll
    for (int m = 0; m < 2; m++)
#pragma unroll
        for (int f = 0; f < 6; f++)
#pragma unroll
            for (int q = 0; q < 4; q++) acc[m][f][q] = 0.f;

    const float4* sB4 = (const float4*)sB;
    const int lslot = lane*3;                 // float4 slot within a k-step
#pragma unroll
    for (int s = 0; s < 12; s++) {
        // 4 x LDS.64: weights (j=2s, 2s+1) for rows r0+8q; j=23 pad gives 0
        float w0[4], w1[4];
#pragma unroll
        for (int q = 0; q < 4; q++) {
            float2 wp = *(const float2*)(sW + (r0 + 8*q)*SWST + 2*s);
            w0[q] = wp.x; w1[q] = wp.y;
        }
        uint32_t a[2][4];
#pragma unroll
        for (int m = 0; m < 2; m++) {
            a[m][0] = tf32u(w0[2*m]   * comp[2*m]);
            a[m][1] = tf32u(w0[2*m+1] * comp[2*m+1]);
            a[m][2] = tf32u(w1[2*m]   * comp[2*m]);
            a[m][3] = tf32u(w1[2*m+1] * comp[2*m+1]);
        }
        // 3 x LDS.128: {b0(f),b1(f)} pairs for f = 0..5 (conflict-free)
        float4 q0 = sB4[s*96 + lslot + 0];
        float4 q1 = sB4[s*96 + lslot + 1];
        float4 q2 = sB4[s*96 + lslot + 2];
        uint32_t b0[6] = { __float_as_uint(q0.x), __float_as_uint(q0.z),
                           __float_as_uint(q1.x), __float_as_uint(q1.z),
                           __float_as_uint(q2.x), __float_as_uint(q2.z) };
        uint32_t b1[6] = { __float_as_uint(q0.y), __float_as_uint(q0.w),
                           __float_as_uint(q1.y), __float_as_uint(q1.w),
                           __float_as_uint(q2.y), __float_as_uint(q2.w) };
#pragma unroll
        for (int f = 0; f < 6; f++) {
            mma8(acc[0][f], a[0][0], a[0][1], a[0][2], a[0][3], b0[f], b1[f]);
            mma8(acc[1][f], a[1][0], a[1][1], a[1][2], a[1][3], b0[f], b1[f]);
        }
    }

    // stage D into smem (aliases sB/sW; conflict-free: bank = (8*tig+g)&31)
    __syncthreads();
#pragma unroll
    for (int m = 0; m < 2; m++) {
        int rA = r0 + 16*m, rB = rA + 8;
#pragma unroll
        for (int f = 0; f < 6; f++) {
            int n0 = 8*f + 2*tig;
            sD[ n0      *SDST + rA] = acc[m][f][0];
            sD[(n0 + 1) *SDST + rA] = acc[m][f][1];
            sD[ n0      *SDST + rB] = acc[m][f][2];
            sD[(n0 + 1) *SDST + rB] = acc[m][f][3];
        }
    }
    __syncthreads();

    // epilogue: warp wid -> poses 2wid, 2wid+1; lane = vertex; 12B-contig STG
#pragma unroll
    for (int pp = 0; pp < 2; pp++) {
        int p = wid*2 + pp;
#pragma unroll
        for (int c = 0; c < 8; c++) {
            int vl = c*32 + lane;
            int vg = v0 + vl;
            if (vg < V) {
                float o0 = sD[(3*p + 0)*SDST + vl];
                float o1 = sD[(3*p + 1)*SDST + vl];
                float o2 = sD[(3*p + 2)*SDST + vl];
                float* dst = out + ((size_t)p*V + vg)*3;
                dst[0] = o0; dst[1] = o1; dst[2] = o2;
            }
        }
    }
}

// ---------------------------------------------------------------------------
extern "C" void kernel_launch(void* const* d_in, const int* in_sizes, int n_in,
                              void* d_out, int out_size)
{
    const float* verts   = (const float*)d_in[0];
    const float* joints  = (const float*)d_in[1];
    const float* weights = (const float*)d_in[2];
    const float* disp    = (const float*)d_in[3];
    const float* rdis    = (const float*)d_in[4];

    int V = in_sizes[0] / 3;
    float* out = (float*)d_out;
    float* out_joints = out + (size_t)out_size - (size_t)NP * NJ * 3;

    cudaFuncSetAttribute(lbs_mma, cudaFuncAttributeMaxDynamicSharedMemorySize, SMEM_BYTES);

    pose_kernel<<<1, 384>>>(joints, disp, rdis,
                            (const float*)d_in[5],  (const float*)d_in[6],
                            (const float*)d_in[7],  (const float*)d_in[8],
                            (const float*)d_in[9],  (const float*)d_in[10],
                            (const float*)d_in[11], (const float*)d_in[12],
                            (const float*)d_in[13], (const float*)d_in[14],
                            (const float*)d_in[15],
                            out_joints);

    int blocks = (V + NT - 1) / NT;
    lbs_mma<<<blocks, 256, SMEM_BYTES>>>(verts, weights, out, V);
}